// round 11
// baseline (speedup 1.0000x reference)
#include <cuda_runtime.h>
#include <cstdint>

// Problem constants (fixed by the reference config)
#define DM 8       // d_model
#define TT 33      // seq_len
#define FFD 28     // d_ff
#define RR 3       // ffn_rank
#define NMODELS 8
#define NBATCH 4096

#define NSEQ 8                    // sequences per block
#define NTHREADS 256              // 8 full warps; slot0 lanes also run t=32
#define BLOCKS_PER_MODEL (NBATCH / NSEQ)   // 512
#define NBLOCKS (NMODELS * BLOCKS_PER_MODEL)

// Per-sequence KV row stride in floats: TT*16 + 4 = 532 (conflict-free octet
// access under the s-fast lane mapping; verified in R5/R6).
#define KVSTRIDE (TT*16 + 4)

typedef unsigned long long u64;

// ---- TF32 rounding (matches reference's TF32 tensor-core einsums) ----
__device__ __forceinline__ float tf32r(float x) {
    uint32_t y;
    asm("cvt.rna.tf32.f32 %0, %1;" : "=r"(y) : "f"(x));
    return __uint_as_float(y);
}

// ---- packed f32x2 ops (sm_100+): one instruction, two FMAs ----
__device__ __forceinline__ u64 pk2(float lo, float hi) {
    u64 r; asm("mov.b64 %0, {%1, %2};" : "=l"(r) : "f"(lo), "f"(hi)); return r;
}
__device__ __forceinline__ void upk2(u64 v, float& lo, float& hi) {
    asm("mov.b64 {%0, %1}, %2;" : "=f"(lo), "=f"(hi) : "l"(v));
}
__device__ __forceinline__ u64 fma2(u64 a, u64 b, u64 c) {
    u64 d; asm("fma.rn.f32x2 %0, %1, %2, %3;" : "=l"(d) : "l"(a), "l"(b), "l"(c)); return d;
}
__device__ __forceinline__ u64 mul2(u64 a, u64 b) {
    u64 d; asm("mul.rn.f32x2 %0, %1, %2;" : "=l"(d) : "l"(a), "l"(b)); return d;
}

__device__ __forceinline__ float dot8p(const u64* a, const float* w) {
    const ulonglong2* W = (const ulonglong2*)w;
    ulonglong2 w01 = W[0], w23 = W[1];
    u64 acc = mul2(a[0], w01.x);
    acc = fma2(a[1], w01.y, acc);
    acc = fma2(a[2], w23.x, acc);
    acc = fma2(a[3], w23.y, acc);
    float lo, hi; upk2(acc, lo, hi);
    return lo + hi;
}

// Exact-erf GELU via Abramowitz-Stegun 7.1.26 (|eps| <= 1.5e-7 abs), branchless.
__device__ __forceinline__ float gelu_ex(float z) {
    float x = z * 0.7071067811865475f;
    float ax = fabsf(x);
    float den = fmaf(0.3275911f, ax, 1.0f);
    float t;
    asm("rcp.approx.f32 %0, %1;" : "=f"(t) : "f"(den));
    float p = fmaf(t, 1.061405429f, -1.453152027f);
    p = fmaf(t, p, 1.421413741f);
    p = fmaf(t, p, -0.284496736f);
    p = fmaf(t, p, 0.254829592f);
    p = p * t;
    float e = __expf(-x * x);
    float erfa = fmaf(-p, e, 1.0f);
    float erfv = copysignf(erfa, z);
    return 0.5f * z * (1.0f + erfv);
}

__global__ __launch_bounds__(NTHREADS, 5)   // 5 blocks/SM target (51 regs)
void block_fused_kernel(
    const float* __restrict__ gx,
    const float* __restrict__ gln1w, const float* __restrict__ gln1b,
    const float* __restrict__ gqkv,  const float* __restrict__ gproj,
    const float* __restrict__ gln2w, const float* __restrict__ gln2b,
    const float* __restrict__ gf1A,  const float* __restrict__ gf1B,
    const float* __restrict__ gf1W,  const float* __restrict__ gf2A,
    const float* __restrict__ gf2B,  const float* __restrict__ gf2W,
    float* __restrict__ gout)
{
    __shared__ __align__(16) float s_qkvT[3*DM][DM];   // [o][i]
    __shared__ __align__(16) float s_projT[DM][DM];    // [o][i]
    __shared__ __align__(16) float s_W1c[FFD][DM];     // [f][i] = f1Wf + f1A@f1B
    __shared__ __align__(16) float s_W2c[FFD][DM];     // [f][d] = f2Wf + f2A@f2B
    __shared__ __align__(16) float s_ln[4][DM];        // ln1w, ln1b, ln2w, ln2b
    __shared__ __align__(16) float s_kv[NSEQ][KVSTRIDE]; // per token: K(8) | V(8)

    const int tid = threadIdx.x;
    const int m  = blockIdx.x / BLOCKS_PER_MODEL;
    const int b0 = (blockIdx.x % BLOCKS_PER_MODEL) * NSEQ;

    // ---- stage weights (TF32-rounded; transposed; low-rank terms folded) ----
    for (int idx = tid; idx < 3*DM*DM; idx += NTHREADS) {
        int o = idx / DM, i = idx % DM;
        s_qkvT[o][i] = tf32r(gqkv[((long)m*DM + i)*(3*DM) + o]);
    }
    for (int idx = tid; idx < DM*DM; idx += NTHREADS) {
        int o = idx / DM, i = idx % DM;
        s_projT[o][i] = tf32r(gproj[((long)m*DM + i)*DM + o]);
    }
    for (int idx = tid; idx < FFD*DM; idx += NTHREADS) {
        int f = idx / DM, i = idx % DM;
        float acc = gf1W[((long)m*DM + i)*FFD + f];
        #pragma unroll
        for (int r = 0; r < RR; r++)
            acc = fmaf(gf1A[((long)m*DM + i)*RR + r],
                       gf1B[((long)m*RR + r)*FFD + f], acc);
        s_W1c[f][i] = tf32r(acc);
    }
    for (int idx = tid; idx < FFD*DM; idx += NTHREADS) {
        int f = idx / DM, d = idx % DM;
        float acc = gf2W[((long)m*FFD + f)*DM + d];
        #pragma unroll
        for (int r = 0; r < RR; r++)
            acc = fmaf(gf2A[((long)m*FFD + f)*RR + r],
                       gf2B[((long)m*RR + r)*DM + d], acc);
        s_W2c[f][d] = tf32r(acc);
    }
    for (int idx = tid; idx < 4*DM; idx += NTHREADS) {
        int which = idx / DM, i = idx % DM;
        const float* src = (which == 0) ? gln1w : (which == 1) ? gln1b
                         : (which == 2) ? gln2w : gln2b;
        s_ln[which][i] = src[(long)m*DM + i];
    }

    __syncthreads();  // staging visible before any weight reads

    const int s    = tid & 7;    // sequence
    const int slot = tid >> 3;   // token slot 0..31
    const long seqbase = (((long)m*NBATCH + b0 + s)*TT) * DM;
    const float qscale = 0.3535533905932738f;  // 1/sqrt(8)

    // ---- per-token pipeline pieces (lambdas; no __syncthreads inside) ----
    auto qkv_tok = [&](int t, u64* qp, float* xr) {
        const long base = seqbase + (long)t * DM;
        float4 a0 = *(const float4*)(gx + base);
        float4 a1 = *(const float4*)(gx + base + 4);
        xr[0]=a0.x; xr[1]=a0.y; xr[2]=a0.z; xr[3]=a0.w;
        xr[4]=a1.x; xr[5]=a1.y; xr[6]=a1.z; xr[7]=a1.w;

        float mean = 0.f;
        #pragma unroll
        for (int i = 0; i < 8; i++) mean += xr[i];
        mean *= 0.125f;
        float var = 0.f;
        #pragma unroll
        for (int i = 0; i < 8; i++) { float d = xr[i] - mean; var += d*d; }
        var *= 0.125f;
        float rstd = rsqrtf(var + 1e-5f);
        float h[8];
        #pragma unroll
        for (int i = 0; i < 8; i++)
            h[i] = tf32r((xr[i] - mean) * rstd * s_ln[0][i] + s_ln[1][i]);
        u64 hp[4];
        #pragma unroll
        for (int i = 0; i < 4; i++) hp[i] = pk2(h[2*i], h[2*i+1]);

        float q[8];
        #pragma unroll
        for (int o = 0; o < 8; o++) q[o] = tf32r(dot8p(hp, s_qkvT[o])) * qscale;
        #pragma unroll
        for (int i = 0; i < 4; i++) qp[i] = pk2(q[2*i], q[2*i+1]);

        float kvv[16];
        #pragma unroll
        for (int o = 0; o < 8; o++) kvv[o]     = tf32r(dot8p(hp, s_qkvT[8 + o]));
        #pragma unroll
        for (int o = 0; o < 8; o++) kvv[8 + o] = tf32r(dot8p(hp, s_qkvT[16 + o]));
        float* dst = &s_kv[s][t*16];
        #pragma unroll
        for (int i = 0; i < 4; i++)
            ((float4*)dst)[i] = make_float4(kvv[4*i], kvv[4*i+1], kvv[4*i+2], kvv[4*i+3]);
    };

    auto attn_mlp_tok = [&](int t, const u64* qp, const float* xr) {
        const long base = seqbase + (long)t * DM;
        // single-pass causal attention (scores tiny => no max subtraction)
        u64 a01 = 0, a23 = 0, a45 = 0, a67 = 0;
        float l = 0.f;
        const float* kvp = &s_kv[s][0];
        for (int j = 0; j <= t; j++) {
            const ulonglong2* kj = (const ulonglong2*)(kvp + j*16);
            ulonglong2 k01 = kj[0], k23 = kj[1];
            u64 d2 = mul2(qp[0], k01.x);
            d2 = fma2(qp[1], k01.y, d2);
            d2 = fma2(qp[2], k23.x, d2);
            d2 = fma2(qp[3], k23.y, d2);
            float lo, hi; upk2(d2, lo, hi);
            float e = __expf(lo + hi);
            l += e;
            u64 e2 = pk2(e, e);
            ulonglong2 v01 = kj[2], v23 = kj[3];
            a01 = fma2(e2, v01.x, a01);
            a23 = fma2(e2, v01.y, a23);
            a45 = fma2(e2, v23.x, a45);
            a67 = fma2(e2, v23.y, a67);
        }
        u64 yp[4];
        {
            float inv_l = 1.f / l;
            float acc[8];
            upk2(a01, acc[0], acc[1]); upk2(a23, acc[2], acc[3]);
            upk2(a45, acc[4], acc[5]); upk2(a67, acc[6], acc[7]);
            #pragma unroll
            for (int i = 0; i < 4; i++)
                yp[i] = pk2(tf32r(acc[2*i] * inv_l), tf32r(acc[2*i+1] * inv_l));
        }

        float xa[8];
        #pragma unroll
        for (int o = 0; o < 8; o++) xa[o] = xr[o] + dot8p(yp, s_projT[o]);

        u64 h2p[4];
        {
            float mean = 0.f;
            #pragma unroll
            for (int i = 0; i < 8; i++) mean += xa[i];
            mean *= 0.125f;
            float var = 0.f;
            #pragma unroll
            for (int i = 0; i < 8; i++) { float d = xa[i] - mean; var += d*d; }
            var *= 0.125f;
            float rstd = rsqrtf(var + 1e-5f);
            float h2[8];
            #pragma unroll
            for (int i = 0; i < 8; i++)
                h2[i] = tf32r((xa[i] - mean) * rstd * s_ln[2][i] + s_ln[3][i]);
            #pragma unroll
            for (int i = 0; i < 4; i++) h2p[i] = pk2(h2[2*i], h2[2*i+1]);
        }

        u64 o01 = 0, o23 = 0, o45 = 0, o67 = 0;
        #pragma unroll
        for (int f = 0; f < FFD; f++) {
            float z = dot8p(h2p, s_W1c[f]);
            z = tf32r(gelu_ex(z));
            u64 z2 = pk2(z, z);
            const ulonglong2* W2 = (const ulonglong2*)s_W2c[f];
            ulonglong2 w01 = W2[0], w23 = W2[1];
            o01 = fma2(z2, w01.x, o01);
            o23 = fma2(z2, w01.y, o23);
            o45 = fma2(z2, w23.x, o45);
            o67 = fma2(z2, w23.y, o67);
        }
        float o8[8];
        upk2(o01, o8[0], o8[1]); upk2(o23, o8[2], o8[3]);
        upk2(o45, o8[4], o8[5]); upk2(o67, o8[6], o8[7]);

        *(float4*)(gout + base)     = make_float4(xa[0]+o8[0], xa[1]+o8[1], xa[2]+o8[2], xa[3]+o8[3]);
        *(float4*)(gout + base + 4) = make_float4(xa[4]+o8[4], xa[5]+o8[5], xa[6]+o8[6], xa[7]+o8[7]);
    };

    // Pass 1: tokens 0..31 (one per thread)
    u64 qp[4];
    float xr[8];
    qkv_tok(slot, qp, xr);
    __syncthreads();   // all KV rows 0..31 visible to all threads
    attn_mlp_tok(slot, qp, xr);

    // Pass 2: token 32 on slot-0 lanes (warp 0). Its KV row is written and
    // read by the SAME thread; reads of rows 0..31 are covered by the sync.
    if (slot == 0) {
        u64 qp2[4];
        float xr2[8];
        qkv_tok(TT - 1, qp2, xr2);
        attn_mlp_tok(TT - 1, qp2, xr2);
    }
}

extern "C" void kernel_launch(void* const* d_in, const int* in_sizes, int n_in,
                              void* d_out, int out_size) {
    const float* x     = (const float*)d_in[0];
    const float* ln1w  = (const float*)d_in[1];
    const float* ln1b  = (const float*)d_in[2];
    const float* qkvw  = (const float*)d_in[3];
    const float* projw = (const float*)d_in[4];
    const float* ln2w  = (const float*)d_in[5];
    const float* ln2b  = (const float*)d_in[6];
    const float* f1A   = (const float*)d_in[7];
    const float* f1B   = (const float*)d_in[8];
    const float* f1W   = (const float*)d_in[9];
    const float* f2A   = (const float*)d_in[10];
    const float* f2B   = (const float*)d_in[11];
    const float* f2W   = (const float*)d_in[12];
    float* out = (float*)d_out;

    block_fused_kernel<<<NBLOCKS, NTHREADS>>>(
        x, ln1w, ln1b, qkvw, projw, ln2w, ln2b,
        f1A, f1B, f1W, f2A, f2B, f2W, out);
}

// round 12
// speedup vs baseline: 5.0503x; 5.0503x over previous
#include <cuda_runtime.h>
#include <cstdint>

// Problem constants (fixed by the reference config)
#define DM 8       // d_model
#define TT 33      // seq_len
#define FFD 28     // d_ff
#define RR 3       // ffn_rank
#define NMODELS 8
#define NBATCH 4096

#define NSEQ 8                    // sequences per block
#define NTHREADS 256              // 8 FULL warps; slot-0 lanes also run t=32
#define BLOCKS_PER_MODEL (NBATCH / NSEQ)   // 512
#define NBLOCKS (NMODELS * BLOCKS_PER_MODEL)

// Per-sequence KV row stride in floats: TT*16 + 4 = 532 (conflict-free octet
// access under the s-fast lane mapping; verified in R5/R6).
#define KVSTRIDE (TT*16 + 4)

typedef unsigned long long u64;

// ---- TF32 rounding (matches reference's TF32 tensor-core einsums) ----
__device__ __forceinline__ float tf32r(float x) {
    uint32_t y;
    asm("cvt.rna.tf32.f32 %0, %1;" : "=r"(y) : "f"(x));
    return __uint_as_float(y);
}

// ---- packed f32x2 ops (sm_100+): one instruction, two FMAs ----
__device__ __forceinline__ u64 pk2(float lo, float hi) {
    u64 r; asm("mov.b64 %0, {%1, %2};" : "=l"(r) : "f"(lo), "f"(hi)); return r;
}
__device__ __forceinline__ void upk2(u64 v, float& lo, float& hi) {
    asm("mov.b64 {%0, %1}, %2;" : "=f"(lo), "=f"(hi) : "l"(v));
}
__device__ __forceinline__ u64 fma2(u64 a, u64 b, u64 c) {
    u64 d; asm("fma.rn.f32x2 %0, %1, %2, %3;" : "=l"(d) : "l"(a), "l"(b), "l"(c)); return d;
}
__device__ __forceinline__ u64 mul2(u64 a, u64 b) {
    u64 d; asm("mul.rn.f32x2 %0, %1, %2;" : "=l"(d) : "l"(a), "l"(b)); return d;
}

__device__ __forceinline__ float dot8p(const u64* a, const float* w) {
    const ulonglong2* W = (const ulonglong2*)w;
    ulonglong2 w01 = W[0], w23 = W[1];
    u64 acc = mul2(a[0], w01.x);
    acc = fma2(a[1], w01.y, acc);
    acc = fma2(a[2], w23.x, acc);
    acc = fma2(a[3], w23.y, acc);
    float lo, hi; upk2(acc, lo, hi);
    return lo + hi;
}

// Exact-erf GELU via Abramowitz-Stegun 7.1.26 (|eps| <= 1.5e-7 abs), branchless.
__device__ __forceinline__ float gelu_ex(float z) {
    float x = z * 0.7071067811865475f;
    float ax = fabsf(x);
    float den = fmaf(0.3275911f, ax, 1.0f);
    float t;
    asm("rcp.approx.f32 %0, %1;" : "=f"(t) : "f"(den));
    float p = fmaf(t, 1.061405429f, -1.453152027f);
    p = fmaf(t, p, 1.421413741f);
    p = fmaf(t, p, -0.284496736f);
    p = fmaf(t, p, 0.254829592f);
    p = p * t;
    float e = __expf(-x * x);
    float erfa = fmaf(-p, e, 1.0f);
    float erfv = copysignf(erfa, z);
    return 0.5f * z * (1.0f + erfv);
}

__global__ __launch_bounds__(NTHREADS, 4)   // 64-reg cap: ABOVE natural (~56) => no spill
void block_fused_kernel(
    const float* __restrict__ gx,
    const float* __restrict__ gln1w, const float* __restrict__ gln1b,
    const float* __restrict__ gqkv,  const float* __restrict__ gproj,
    const float* __restrict__ gln2w, const float* __restrict__ gln2b,
    const float* __restrict__ gf1A,  const float* __restrict__ gf1B,
    const float* __restrict__ gf1W,  const float* __restrict__ gf2A,
    const float* __restrict__ gf2B,  const float* __restrict__ gf2W,
    float* __restrict__ gout)
{
    __shared__ __align__(16) float s_qkvT[3*DM][DM];   // [o][i]
    __shared__ __align__(16) float s_projT[DM][DM];    // [o][i]
    __shared__ __align__(16) float s_W1c[FFD][DM];     // [f][i] = f1Wf + f1A@f1B
    __shared__ __align__(16) float s_W2c[FFD][DM];     // [f][d] = f2Wf + f2A@f2B
    __shared__ __align__(16) float s_ln[4][DM];        // ln1w, ln1b, ln2w, ln2b
    __shared__ __align__(16) float s_kv[NSEQ][KVSTRIDE]; // per token: K(8) | V(8)

    const int tid = threadIdx.x;
    const int m  = blockIdx.x / BLOCKS_PER_MODEL;
    const int b0 = (blockIdx.x % BLOCKS_PER_MODEL) * NSEQ;

    // ---- stage weights (TF32-rounded; transposed; low-rank terms folded) ----
    for (int idx = tid; idx < 3*DM*DM; idx += NTHREADS) {
        int o = idx / DM, i = idx % DM;
        s_qkvT[o][i] = tf32r(gqkv[((long)m*DM + i)*(3*DM) + o]);
    }
    for (int idx = tid; idx < DM*DM; idx += NTHREADS) {
        int o = idx / DM, i = idx % DM;
        s_projT[o][i] = tf32r(gproj[((long)m*DM + i)*DM + o]);
    }
    for (int idx = tid; idx < FFD*DM; idx += NTHREADS) {
        int f = idx / DM, i = idx % DM;
        float acc = gf1W[((long)m*DM + i)*FFD + f];
        #pragma unroll
        for (int r = 0; r < RR; r++)
            acc = fmaf(gf1A[((long)m*DM + i)*RR + r],
                       gf1B[((long)m*RR + r)*FFD + f], acc);
        s_W1c[f][i] = tf32r(acc);
    }
    for (int idx = tid; idx < FFD*DM; idx += NTHREADS) {
        int f = idx / DM, d = idx % DM;
        float acc = gf2W[((long)m*FFD + f)*DM + d];
        #pragma unroll
        for (int r = 0; r < RR; r++)
            acc = fmaf(gf2A[((long)m*FFD + f)*RR + r],
                       gf2B[((long)m*RR + r)*DM + d], acc);
        s_W2c[f][d] = tf32r(acc);
    }
    for (int idx = tid; idx < 4*DM; idx += NTHREADS) {
        int which = idx / DM, i = idx % DM;
        const float* src = (which == 0) ? gln1w : (which == 1) ? gln1b
                         : (which == 2) ? gln2w : gln2b;
        s_ln[which][i] = src[(long)m*DM + i];
    }

    __syncthreads();  // staging visible before any weight reads

    const int s    = tid & 7;    // sequence
    const int slot = tid >> 3;   // token slot 0..31
    const long seqbase = (((long)m*NBATCH + b0 + s)*TT) * DM;
    const float qscale = 0.3535533905932738f;  // 1/sqrt(8)

    // Two passes through ONE code instance (unroll 1 keeps reg pressure at the
    // single-token level; R11's inlined duplicate + tight reg cap spilled).
    // pass 0: t = slot (all threads); pass 1: t = 32 (slot-0 lanes only).
    #pragma unroll 1
    for (int pass = 0; pass < 2; pass++) {
        if (pass == 1 && slot != 0) break;
        const int t = (pass == 0) ? slot : (TT - 1);
        const long base = seqbase + (long)t * DM;

        // ---- LN1 + QKV ----
        float xr[8];
        u64 qp[4];
        {
            float4 a0 = *(const float4*)(gx + base);
            float4 a1 = *(const float4*)(gx + base + 4);
            xr[0]=a0.x; xr[1]=a0.y; xr[2]=a0.z; xr[3]=a0.w;
            xr[4]=a1.x; xr[5]=a1.y; xr[6]=a1.z; xr[7]=a1.w;

            float mean = 0.f;
            #pragma unroll
            for (int i = 0; i < 8; i++) mean += xr[i];
            mean *= 0.125f;
            float var = 0.f;
            #pragma unroll
            for (int i = 0; i < 8; i++) { float d = xr[i] - mean; var += d*d; }
            var *= 0.125f;
            float rstd = rsqrtf(var + 1e-5f);
            float h[8];
            #pragma unroll
            for (int i = 0; i < 8; i++)
                h[i] = tf32r((xr[i] - mean) * rstd * s_ln[0][i] + s_ln[1][i]);
            u64 hp[4];
            #pragma unroll
            for (int i = 0; i < 4; i++) hp[i] = pk2(h[2*i], h[2*i+1]);

            float q[8];
            #pragma unroll
            for (int o = 0; o < 8; o++) q[o] = tf32r(dot8p(hp, s_qkvT[o])) * qscale;
            #pragma unroll
            for (int i = 0; i < 4; i++) qp[i] = pk2(q[2*i], q[2*i+1]);

            float kvv[16];
            #pragma unroll
            for (int o = 0; o < 8; o++) kvv[o]     = tf32r(dot8p(hp, s_qkvT[8 + o]));
            #pragma unroll
            for (int o = 0; o < 8; o++) kvv[8 + o] = tf32r(dot8p(hp, s_qkvT[16 + o]));
            float* dst = &s_kv[s][t*16];
            #pragma unroll
            for (int i = 0; i < 4; i++)
                ((float4*)dst)[i] = make_float4(kvv[4*i], kvv[4*i+1], kvv[4*i+2], kvv[4*i+3]);
        }

        // Barrier only on pass 0 (uniform: ALL threads execute pass 0).
        // Pass 1's KV row 32 is same-thread write->read; rows 0..31 were
        // ordered by this barrier already.
        if (pass == 0) __syncthreads();

        // ---- single-pass causal attention (tiny scores => no max) ----
        u64 a01 = 0, a23 = 0, a45 = 0, a67 = 0;
        float l = 0.f;
        {
            const float* kvp = &s_kv[s][0];
            for (int j = 0; j <= t; j++) {
                const ulonglong2* kj = (const ulonglong2*)(kvp + j*16);
                ulonglong2 k01 = kj[0], k23 = kj[1];
                u64 d2 = mul2(qp[0], k01.x);
                d2 = fma2(qp[1], k01.y, d2);
                d2 = fma2(qp[2], k23.x, d2);
                d2 = fma2(qp[3], k23.y, d2);
                float lo, hi; upk2(d2, lo, hi);
                float e = __expf(lo + hi);
                l += e;
                u64 e2 = pk2(e, e);
                ulonglong2 v01 = kj[2], v23 = kj[3];
                a01 = fma2(e2, v01.x, a01);
                a23 = fma2(e2, v01.y, a23);
                a45 = fma2(e2, v23.x, a45);
                a67 = fma2(e2, v23.y, a67);
            }
        }
        u64 yp[4];
        {
            float inv_l = 1.f / l;
            float acc[8];
            upk2(a01, acc[0], acc[1]); upk2(a23, acc[2], acc[3]);
            upk2(a45, acc[4], acc[5]); upk2(a67, acc[6], acc[7]);
            #pragma unroll
            for (int i = 0; i < 4; i++)
                yp[i] = pk2(tf32r(acc[2*i] * inv_l), tf32r(acc[2*i+1] * inv_l));
        }

        // ---- proj + residual ----
        float xa[8];
        #pragma unroll
        for (int o = 0; o < 8; o++) xa[o] = xr[o] + dot8p(yp, s_projT[o]);

        // ---- LN2 ----
        u64 h2p[4];
        {
            float mean = 0.f;
            #pragma unroll
            for (int i = 0; i < 8; i++) mean += xa[i];
            mean *= 0.125f;
            float var = 0.f;
            #pragma unroll
            for (int i = 0; i < 8; i++) { float d = xa[i] - mean; var += d*d; }
            var *= 0.125f;
            float rstd = rsqrtf(var + 1e-5f);
            float h2[8];
            #pragma unroll
            for (int i = 0; i < 8; i++)
                h2[i] = tf32r((xa[i] - mean) * rstd * s_ln[2][i] + s_ln[3][i]);
            #pragma unroll
            for (int i = 0; i < 4; i++) h2p[i] = pk2(h2[2*i], h2[2*i+1]);
        }

        // ---- MLP: out = xa + gelu(h2 @ W1c) @ W2c ----
        u64 o01 = 0, o23 = 0, o45 = 0, o67 = 0;
        #pragma unroll
        for (int f = 0; f < FFD; f++) {
            float z = dot8p(h2p, s_W1c[f]);
            z = tf32r(gelu_ex(z));
            u64 z2 = pk2(z, z);
            const ulonglong2* W2 = (const ulonglong2*)s_W2c[f];
            ulonglong2 w01 = W2[0], w23 = W2[1];
            o01 = fma2(z2, w01.x, o01);
            o23 = fma2(z2, w01.y, o23);
            o45 = fma2(z2, w23.x, o45);
            o67 = fma2(z2, w23.y, o67);
        }
        float o8[8];
        upk2(o01, o8[0], o8[1]); upk2(o23, o8[2], o8[3]);
        upk2(o45, o8[4], o8[5]); upk2(o67, o8[6], o8[7]);

        *(float4*)(gout + base)     = make_float4(xa[0]+o8[0], xa[1]+o8[1], xa[2]+o8[2], xa[3]+o8[3]);
        *(float4*)(gout + base + 4) = make_float4(xa[4]+o8[4], xa[5]+o8[5], xa[6]+o8[6], xa[7]+o8[7]);
    }
}

extern "C" void kernel_launch(void* const* d_in, const int* in_sizes, int n_in,
                              void* d_out, int out_size) {
    const float* x     = (const float*)d_in[0];
    const float* ln1w  = (const float*)d_in[1];
    const float* ln1b  = (const float*)d_in[2];
    const float* qkvw  = (const float*)d_in[3];
    const float* projw = (const float*)d_in[4];
    const float* ln2w  = (const float*)d_in[5];
    const float* ln2b  = (const float*)d_in[6];
    const float* f1A   = (const float*)d_in[7];
    const float* f1B   = (const float*)d_in[8];
    const float* f1W   = (const float*)d_in[9];
    const float* f2A   = (const float*)d_in[10];
    const float* f2B   = (const float*)d_in[11];
    const float* f2W   = (const float*)d_in[12];
    float* out = (float*)d_out;

    block_fused_kernel<<<NBLOCKS, NTHREADS>>>(
        x, ln1w, ln1b, qkvw, projw, ln2w, ln2b,
        f1A, f1B, f1W, f2A, f2B, f2W, out);
}

// round 14
// speedup vs baseline: 6.0894x; 1.2057x over previous
#include <cuda_runtime.h>
#include <cuda_bf16.h>
#include <cstdint>

// Problem constants (fixed by the reference config)
#define DM 8       // d_model
#define TT 33      // seq_len
#define FFD 28     // d_ff
#define RR 3       // ffn_rank
#define NMODELS 8
#define NBATCH 4096

#define NSEQ 8                    // sequences per block
#define NTHREADS (TT * NSEQ)      // 264 threads (R10 shape — best measured)
#define BLOCKS_PER_MODEL (NBATCH / NSEQ)   // 512
#define NBLOCKS (NMODELS * BLOCKS_PER_MODEL)

// KV row per token: 8 bf16 K (16B) + 8 bf16 V (16B) = 8 words.
// Per-seq stride in words: 33*8 = 264, padded to 292 (292 mod 32 = 4 =>
// lane s offset s*4 mod 32 covers 8 distinct bank quads; conflict-free).
#define KVSTRIDE 292

typedef unsigned long long u64;

// ---- TF32 rounding (MLP path matches reference's TF32 einsums) ----
__device__ __forceinline__ float tf32r(float x) {
    uint32_t y;
    asm("cvt.rna.tf32.f32 %0, %1;" : "=r"(y) : "f"(x));
    return __uint_as_float(y);
}

// ---- packed f32x2 ops (sm_100+) for the fp32 MLP path ----
__device__ __forceinline__ u64 pk2(float lo, float hi) {
    u64 r; asm("mov.b64 %0, {%1, %2};" : "=l"(r) : "f"(lo), "f"(hi)); return r;
}
__device__ __forceinline__ void upk2(u64 v, float& lo, float& hi) {
    asm("mov.b64 {%0, %1}, %2;" : "=f"(lo), "=f"(hi) : "l"(v));
}
__device__ __forceinline__ u64 fma2(u64 a, u64 b, u64 c) {
    u64 d; asm("fma.rn.f32x2 %0, %1, %2, %3;" : "=l"(d) : "l"(a), "l"(b), "l"(c)); return d;
}
__device__ __forceinline__ u64 mul2(u64 a, u64 b) {
    u64 d; asm("mul.rn.f32x2 %0, %1, %2;" : "=l"(d) : "l"(a), "l"(b)); return d;
}

__device__ __forceinline__ float dot8p(const u64* a, const float* w) {
    const ulonglong2* W = (const ulonglong2*)w;
    ulonglong2 w01 = W[0], w23 = W[1];
    u64 acc = mul2(a[0], w01.x);
    acc = fma2(a[1], w01.y, acc);
    acc = fma2(a[2], w23.x, acc);
    acc = fma2(a[3], w23.y, acc);
    float lo, hi; upk2(acc, lo, hi);
    return lo + hi;
}

// ---- bf16 helpers (attention path; branch weight ~1e-3 => bf16 is safe) ----
// dot of 4 bf162 activation pairs with a 16B bf16 weight row (one LDS.128)
__device__ __forceinline__ float dot8b(const __nv_bfloat162* a, const __nv_bfloat16* w) {
    float4 wv = *(const float4*)w;
    __nv_bfloat162 w0 = *reinterpret_cast<__nv_bfloat162*>(&wv.x);
    __nv_bfloat162 w1 = *reinterpret_cast<__nv_bfloat162*>(&wv.y);
    __nv_bfloat162 w2 = *reinterpret_cast<__nv_bfloat162*>(&wv.z);
    __nv_bfloat162 w3 = *reinterpret_cast<__nv_bfloat162*>(&wv.w);
    __nv_bfloat162 acc = __hmul2(a[0], w0);
    acc = __hfma2(a[1], w1, acc);
    acc = __hfma2(a[2], w2, acc);
    acc = __hfma2(a[3], w3, acc);
    float2 f = __bfloat1622float2(acc);
    return f.x + f.y;
}

// Exact-erf GELU via Abramowitz-Stegun 7.1.26 (|eps| <= 1.5e-7 abs), branchless.
__device__ __forceinline__ float gelu_ex(float z) {
    float x = z * 0.7071067811865475f;
    float ax = fabsf(x);
    float den = fmaf(0.3275911f, ax, 1.0f);
    float t;
    asm("rcp.approx.f32 %0, %1;" : "=f"(t) : "f"(den));
    float p = fmaf(t, 1.061405429f, -1.453152027f);
    p = fmaf(t, p, 1.421413741f);
    p = fmaf(t, p, -0.284496736f);
    p = fmaf(t, p, 0.254829592f);
    p = p * t;
    float e = __expf(-x * x);
    float erfa = fmaf(-p, e, 1.0f);
    float erfv = copysignf(erfa, z);
    return 0.5f * z * (1.0f + erfv);
}

__global__ __launch_bounds__(NTHREADS, 4)
void block_fused_kernel(
    const float* __restrict__ gx,
    const float* __restrict__ gln1w, const float* __restrict__ gln1b,
    const float* __restrict__ gqkv,  const float* __restrict__ gproj,
    const float* __restrict__ gln2w, const float* __restrict__ gln2b,
    const float* __restrict__ gf1A,  const float* __restrict__ gf1B,
    const float* __restrict__ gf1W,  const float* __restrict__ gf2A,
    const float* __restrict__ gf2B,  const float* __restrict__ gf2W,
    float* __restrict__ gout)
{
    // Attention-path weights in bf16 (16B rows); MLP weights stay fp32/tf32.
    __shared__ __align__(16) __nv_bfloat16 s_qkvTb[3*DM][DM]; // [o][i]
    __shared__ __align__(16) __nv_bfloat16 s_projTb[DM][DM];  // [o][i]
    __shared__ __align__(16) float s_W1c[FFD][DM];     // [f][i] = f1Wf + f1A@f1B
    __shared__ __align__(16) float s_W2c[FFD][DM];     // [f][d] = f2Wf + f2A@f2B
    __shared__ __align__(16) float s_ln[4][DM];        // ln1w, ln1b, ln2w, ln2b
    __shared__ __align__(16) float s_kv[NSEQ][KVSTRIDE]; // bf16 K(16B)|V(16B) per token

    const int tid = threadIdx.x;
    const int m  = blockIdx.x / BLOCKS_PER_MODEL;
    const int b0 = (blockIdx.x % BLOCKS_PER_MODEL) * NSEQ;

    // ---- stage weights ----
    for (int idx = tid; idx < 3*DM*DM; idx += NTHREADS) {
        int o = idx / DM, i = idx % DM;
        s_qkvTb[o][i] = __float2bfloat16(gqkv[((long)m*DM + i)*(3*DM) + o]);
    }
    for (int idx = tid; idx < DM*DM; idx += NTHREADS) {
        int o = idx / DM, i = idx % DM;
        s_projTb[o][i] = __float2bfloat16(gproj[((long)m*DM + i)*DM + o]);
    }
    for (int idx = tid; idx < FFD*DM; idx += NTHREADS) {
        int f = idx / DM, i = idx % DM;
        float acc = gf1W[((long)m*DM + i)*FFD + f];
        #pragma unroll
        for (int r = 0; r < RR; r++)
            acc = fmaf(gf1A[((long)m*DM + i)*RR + r],
                       gf1B[((long)m*RR + r)*FFD + f], acc);
        s_W1c[f][i] = tf32r(acc);
    }
    for (int idx = tid; idx < FFD*DM; idx += NTHREADS) {
        int f = idx / DM, d = idx % DM;
        float acc = gf2W[((long)m*FFD + f)*DM + d];
        #pragma unroll
        for (int r = 0; r < RR; r++)
            acc = fmaf(gf2A[((long)m*FFD + f)*RR + r],
                       gf2B[((long)m*RR + r)*DM + d], acc);
        s_W2c[f][d] = tf32r(acc);
    }
    for (int idx = tid; idx < 4*DM; idx += NTHREADS) {
        int which = idx / DM, i = idx % DM;
        const float* src = (which == 0) ? gln1w : (which == 1) ? gln1b
                         : (which == 2) ? gln2w : gln2b;
        s_ln[which][i] = src[(long)m*DM + i];
    }

    __syncthreads();  // staging visible before any weight reads

    // ---- per-token pipeline (s fast, t slow: minimal warp divergence) ----
    const int s = tid & 7;
    const int t = tid >> 3;
    const long base = ((((long)m*NBATCH + b0 + s)*TT) + t) * DM;

    float4 x0 = *(const float4*)(gx + base);
    float4 x1 = *(const float4*)(gx + base + 4);
    float xr[8] = {x0.x, x0.y, x0.z, x0.w, x1.x, x1.y, x1.z, x1.w};

    // LN1 (exact fp32), output packed to bf16 (feeds only q/k/v: attention branch)
    __nv_bfloat162 hb[4];
    {
        float mean = 0.f;
        #pragma unroll
        for (int i = 0; i < 8; i++) mean += xr[i];
        mean *= 0.125f;
        float var = 0.f;
        #pragma unroll
        for (int i = 0; i < 8; i++) { float d = xr[i] - mean; var += d*d; }
        var *= 0.125f;
        float rstd = rsqrtf(var + 1e-5f);
        float h[8];
        #pragma unroll
        for (int i = 0; i < 8; i++)
            h[i] = (xr[i] - mean) * rstd * s_ln[0][i] + s_ln[1][i];
        #pragma unroll
        for (int i = 0; i < 4; i++) hb[i] = __floats2bfloat162_rn(h[2*i], h[2*i+1]);
    }

    const float qscale = 0.3535533905932738f;  // 1/sqrt(8), applied to the score

    // QKV in bf16; write K|V row (32B) to shared
    __nv_bfloat162 qb[4];
    {
        #pragma unroll
        for (int i = 0; i < 4; i++)
            qb[i] = __floats2bfloat162_rn(dot8b(hb, s_qkvTb[2*i]),
                                          dot8b(hb, s_qkvTb[2*i+1]));
        float kvv[16];
        #pragma unroll
        for (int o = 0; o < 8; o++) kvv[o]     = dot8b(hb, s_qkvTb[8 + o]);
        #pragma unroll
        for (int o = 0; o < 8; o++) kvv[8 + o] = dot8b(hb, s_qkvTb[16 + o]);

        float4 pack[2];
        #pragma unroll
        for (int half = 0; half < 2; half++) {
            __nv_bfloat162 p0 = __floats2bfloat162_rn(kvv[8*half+0], kvv[8*half+1]);
            __nv_bfloat162 p1 = __floats2bfloat162_rn(kvv[8*half+2], kvv[8*half+3]);
            __nv_bfloat162 p2 = __floats2bfloat162_rn(kvv[8*half+4], kvv[8*half+5]);
            __nv_bfloat162 p3 = __floats2bfloat162_rn(kvv[8*half+6], kvv[8*half+7]);
            pack[half] = make_float4(*reinterpret_cast<float*>(&p0),
                                     *reinterpret_cast<float*>(&p1),
                                     *reinterpret_cast<float*>(&p2),
                                     *reinterpret_cast<float*>(&p3));
        }
        float4* dst = (float4*)(&s_kv[s][t*8]);
        dst[0] = pack[0];   // K
        dst[1] = pack[1];   // V
    }
    __syncthreads();

    // Single-pass causal attention, fully bf16 (scores tiny => no max needed;
    // attention branch weight ~1e-3 of output => bf16 error is negligible).
    __nv_bfloat162 av[4] = {__floats2bfloat162_rn(0.f,0.f), __floats2bfloat162_rn(0.f,0.f),
                            __floats2bfloat162_rn(0.f,0.f), __floats2bfloat162_rn(0.f,0.f)};
    float l = 0.f;
    {
        const float* kvp = &s_kv[s][0];
        for (int j = 0; j <= t; j++) {
            const float4* kj = (const float4*)(kvp + j*8);
            float4 kw = kj[0];
            __nv_bfloat162 sc2 = __hmul2(qb[0], *reinterpret_cast<__nv_bfloat162*>(&kw.x));
            sc2 = __hfma2(qb[1], *reinterpret_cast<__nv_bfloat162*>(&kw.y), sc2);
            sc2 = __hfma2(qb[2], *reinterpret_cast<__nv_bfloat162*>(&kw.z), sc2);
            sc2 = __hfma2(qb[3], *reinterpret_cast<__nv_bfloat162*>(&kw.w), sc2);
            float2 sf = __bfloat1622float2(sc2);
            float e = __expf((sf.x + sf.y) * qscale);
            l += e;
            __nv_bfloat162 e2 = __float2bfloat162_rn(e);
            float4 vw = kj[1];
            av[0] = __hfma2(e2, *reinterpret_cast<__nv_bfloat162*>(&vw.x), av[0]);
            av[1] = __hfma2(e2, *reinterpret_cast<__nv_bfloat162*>(&vw.y), av[1]);
            av[2] = __hfma2(e2, *reinterpret_cast<__nv_bfloat162*>(&vw.z), av[2]);
            av[3] = __hfma2(e2, *reinterpret_cast<__nv_bfloat162*>(&vw.w), av[3]);
        }
    }
    __nv_bfloat162 yb[4];
    {
        float inv_l = 1.f / l;
        #pragma unroll
        for (int i = 0; i < 4; i++) {
            float2 f = __bfloat1622float2(av[i]);
            yb[i] = __floats2bfloat162_rn(f.x * inv_l, f.y * inv_l);
        }
    }

    // proj (bf16) + residual (fp32)
    float xa[8];
    #pragma unroll
    for (int o = 0; o < 8; o++) xa[o] = xr[o] + dot8b(yb, s_projTb[o]);

    // LN2 (fp32 stats, TF32-quantized output: feeds the precision-critical MLP)
    u64 h2p[4];
    {
        float mean = 0.f;
        #pragma unroll
        for (int i = 0; i < 8; i++) mean += xa[i];
        mean *= 0.125f;
        float var = 0.f;
        #pragma unroll
        for (int i = 0; i < 8; i++) { float d = xa[i] - mean; var += d*d; }
        var *= 0.125f;
        float rstd = rsqrtf(var + 1e-5f);
        float h2[8];
        #pragma unroll
        for (int i = 0; i < 8; i++)
            h2[i] = tf32r((xa[i] - mean) * rstd * s_ln[2][i] + s_ln[3][i]);
        #pragma unroll
        for (int i = 0; i < 4; i++) h2p[i] = pk2(h2[2*i], h2[2*i+1]);
    }

    // MLP (fp32/tf32 — the dominant-precision branch): out = xa + gelu(h2@W1c)@W2c
    u64 o01 = 0, o23 = 0, o45 = 0, o67 = 0;
    #pragma unroll
    for (int f = 0; f < FFD; f++) {
        float z = dot8p(h2p, s_W1c[f]);
        z = tf32r(gelu_ex(z));
        u64 z2 = pk2(z, z);
        const ulonglong2* W2 = (const ulonglong2*)s_W2c[f];
        ulonglong2 w01 = W2[0], w23 = W2[1];
        o01 = fma2(z2, w01.x, o01);
        o23 = fma2(z2, w01.y, o23);
        o45 = fma2(z2, w23.x, o45);
        o67 = fma2(z2, w23.y, o67);
    }

    float o8[8];
    upk2(o01, o8[0], o8[1]); upk2(o23, o8[2], o8[3]);
    upk2(o45, o8[4], o8[5]); upk2(o67, o8[6], o8[7]);

    *(float4*)(gout + base)     = make_float4(xa[0]+o8[0], xa[1]+o8[1], xa[2]+o8[2], xa[3]+o8[3]);
    *(float4*)(gout + base + 4) = make_float4(xa[4]+o8[4], xa[5]+o8[5], xa[6]+o8[6], xa[7]+o8[7]);
}

extern "C" void kernel_launch(void* const* d_in, const int* in_sizes, int n_in,
                              void* d_out, int out_size) {
    const float* x     = (const float*)d_in[0];
    const float* ln1w  = (const float*)d_in[1];
    const float* ln1b  = (const float*)d_in[2];
    const float* qkvw  = (const float*)d_in[3];
    const float* projw = (const float*)d_in[4];
    const float* ln2w  = (const float*)d_in[5];
    const float* ln2b  = (const float*)d_in[6];
    const float* f1A   = (const float*)d_in[7];
    const float* f1B   = (const float*)d_in[8];
    const float* f1W   = (const float*)d_in[9];
    const float* f2A   = (const float*)d_in[10];
    const float* f2B   = (const float*)d_in[11];
    const float* f2W   = (const float*)d_in[12];
    float* out = (float*)d_out;

    block_fused_kernel<<<NBLOCKS, NTHREADS>>>(
        x, ln1w, ln1b, qkvw, projw, ln2w, ln2b,
        f1A, f1B, f1W, f2A, f2B, f2W, out);
}

// round 15
// speedup vs baseline: 6.3614x; 1.0447x over previous
#include <cuda_runtime.h>
#include <cuda_bf16.h>
#include <cstdint>

// Problem constants (fixed by the reference config)
#define DM 8       // d_model
#define TT 33      // seq_len
#define FFD 28     // d_ff
#define RR 3       // ffn_rank
#define NMODELS 8
#define NBATCH 4096

#define NSEQ 8                    // sequences per block
#define NTHREADS (TT * NSEQ)      // 264 threads (best measured shape)
#define BLOCKS_PER_MODEL (NBATCH / NSEQ)   // 512
#define NBLOCKS (NMODELS * BLOCKS_PER_MODEL)

// KV row per token: 8 bf16 K (16B) + 8 bf16 V (16B) = 8 words.
// Per-seq stride 292 words (292 mod 32 = 4 => conflict-free octet access).
#define KVSTRIDE 292

typedef unsigned long long u64;

// ---- TF32 rounding (MLP path matches reference's TF32 einsums) ----
__device__ __forceinline__ float tf32r(float x) {
    uint32_t y;
    asm("cvt.rna.tf32.f32 %0, %1;" : "=r"(y) : "f"(x));
    return __uint_as_float(y);
}

// ---- packed f32x2 ops (sm_100+) ----
__device__ __forceinline__ u64 pk2(float lo, float hi) {
    u64 r; asm("mov.b64 %0, {%1, %2};" : "=l"(r) : "f"(lo), "f"(hi)); return r;
}
__device__ __forceinline__ void upk2(u64 v, float& lo, float& hi) {
    asm("mov.b64 {%0, %1}, %2;" : "=f"(lo), "=f"(hi) : "l"(v));
}
__device__ __forceinline__ u64 fma2(u64 a, u64 b, u64 c) {
    u64 d; asm("fma.rn.f32x2 %0, %1, %2, %3;" : "=l"(d) : "l"(a), "l"(b), "l"(c)); return d;
}
__device__ __forceinline__ u64 mul2(u64 a, u64 b) {
    u64 d; asm("mul.rn.f32x2 %0, %1, %2;" : "=l"(d) : "l"(a), "l"(b)); return d;
}

__device__ __forceinline__ float rcpa(float x) {
    float y; asm("rcp.approx.f32 %0, %1;" : "=f"(y) : "f"(x)); return y;
}
__device__ __forceinline__ float ex2a(float x) {
    float y; asm("ex2.approx.f32 %0, %1;" : "=f"(y) : "f"(x)); return y;
}

__device__ __forceinline__ float dot8p(const u64* a, const float* w) {
    const ulonglong2* W = (const ulonglong2*)w;
    ulonglong2 w01 = W[0], w23 = W[1];
    u64 acc = mul2(a[0], w01.x);
    acc = fma2(a[1], w01.y, acc);
    acc = fma2(a[2], w23.x, acc);
    acc = fma2(a[3], w23.y, acc);
    float lo, hi; upk2(acc, lo, hi);
    return lo + hi;
}

// ---- bf16 helpers (attention path; branch weight ~1e-3 => bf16 is safe) ----
__device__ __forceinline__ float dot8b(const __nv_bfloat162* a, const __nv_bfloat16* w) {
    float4 wv = *(const float4*)w;
    __nv_bfloat162 w0 = *reinterpret_cast<__nv_bfloat162*>(&wv.x);
    __nv_bfloat162 w1 = *reinterpret_cast<__nv_bfloat162*>(&wv.y);
    __nv_bfloat162 w2 = *reinterpret_cast<__nv_bfloat162*>(&wv.z);
    __nv_bfloat162 w3 = *reinterpret_cast<__nv_bfloat162*>(&wv.w);
    __nv_bfloat162 acc = __hmul2(a[0], w0);
    acc = __hfma2(a[1], w1, acc);
    acc = __hfma2(a[2], w2, acc);
    acc = __hfma2(a[3], w3, acc);
    float2 f = __bfloat1622float2(acc);
    return f.x + f.y;
}

// Packed-pair exact-erf GELU (A&S 7.1.26, |eps|<=1.5e-7): processes two z's
// through one f32x2 pipeline. Only rcp/ex2 are scalar (no packed MUFU).
__device__ __forceinline__ u64 gelu2(u64 z2) {
    const u64 SIGN2 = 0x8000000080000000ull;
    u64 x2 = mul2(z2, pk2(0.7071067811865475f, 0.7071067811865475f));
    u64 ax = x2 & ~SIGN2;                                   // |x| per half
    u64 den = fma2(pk2(0.3275911f, 0.3275911f), ax, pk2(1.f, 1.f));
    float dlo, dhi; upk2(den, dlo, dhi);
    u64 t = pk2(rcpa(dlo), rcpa(dhi));
    u64 p = fma2(t, pk2(1.061405429f, 1.061405429f), pk2(-1.453152027f, -1.453152027f));
    p = fma2(t, p, pk2(1.421413741f, 1.421413741f));
    p = fma2(t, p, pk2(-0.284496736f, -0.284496736f));
    p = fma2(t, p, pk2(0.254829592f, 0.254829592f));
    p = mul2(p, t);
    u64 xx = mul2(x2, x2);
    u64 w  = mul2(xx, pk2(-1.4426950408889634f, -1.4426950408889634f)); // -x^2*log2e
    float wlo, whi; upk2(w, wlo, whi);
    u64 e = pk2(ex2a(wlo), ex2a(whi));                      // exp(-x^2)
    u64 erfa = fma2(p ^ SIGN2, e, pk2(1.f, 1.f));           // 1 - p*e = erf(|x|) >= 0
    u64 erfv = erfa | (z2 & SIGN2);                         // copysign(erf, z)
    u64 sfac = fma2(erfv, pk2(0.5f, 0.5f), pk2(0.5f, 0.5f));
    return mul2(z2, sfac);                                  // z * 0.5*(1+erf)
}

__global__ __launch_bounds__(NTHREADS, 4)
void block_fused_kernel(
    const float* __restrict__ gx,
    const float* __restrict__ gln1w, const float* __restrict__ gln1b,
    const float* __restrict__ gqkv,  const float* __restrict__ gproj,
    const float* __restrict__ gln2w, const float* __restrict__ gln2b,
    const float* __restrict__ gf1A,  const float* __restrict__ gf1B,
    const float* __restrict__ gf1W,  const float* __restrict__ gf2A,
    const float* __restrict__ gf2B,  const float* __restrict__ gf2W,
    float* __restrict__ gout)
{
    // Attention-path weights in bf16 (16B rows); MLP weights stay fp32/tf32.
    __shared__ __align__(16) __nv_bfloat16 s_qkvTb[3*DM][DM]; // [o][i]
    __shared__ __align__(16) __nv_bfloat16 s_projTb[DM][DM];  // [o][i]
    __shared__ __align__(16) float s_W1c[FFD][DM];     // [f][i] = f1Wf + f1A@f1B
    __shared__ __align__(16) float s_W2c[FFD][DM];     // [f][d] = f2Wf + f2A@f2B
    __shared__ __align__(16) float s_ln[4][DM];        // ln1w, ln1b, ln2w, ln2b
    __shared__ __align__(16) float s_kv[NSEQ][KVSTRIDE]; // bf16 K(16B)|V(16B) per token

    const int tid = threadIdx.x;
    const int m  = blockIdx.x / BLOCKS_PER_MODEL;
    const int b0 = (blockIdx.x % BLOCKS_PER_MODEL) * NSEQ;

    // ---- stage weights ----
    for (int idx = tid; idx < 3*DM*DM; idx += NTHREADS) {
        int o = idx / DM, i = idx % DM;
        s_qkvTb[o][i] = __float2bfloat16(gqkv[((long)m*DM + i)*(3*DM) + o]);
    }
    for (int idx = tid; idx < DM*DM; idx += NTHREADS) {
        int o = idx / DM, i = idx % DM;
        s_projTb[o][i] = __float2bfloat16(gproj[((long)m*DM + i)*DM + o]);
    }
    for (int idx = tid; idx < FFD*DM; idx += NTHREADS) {
        int f = idx / DM, i = idx % DM;
        float acc = gf1W[((long)m*DM + i)*FFD + f];
        #pragma unroll
        for (int r = 0; r < RR; r++)
            acc = fmaf(gf1A[((long)m*DM + i)*RR + r],
                       gf1B[((long)m*RR + r)*FFD + f], acc);
        s_W1c[f][i] = tf32r(acc);
    }
    for (int idx = tid; idx < FFD*DM; idx += NTHREADS) {
        int f = idx / DM, d = idx % DM;
        float acc = gf2W[((long)m*FFD + f)*DM + d];
        #pragma unroll
        for (int r = 0; r < RR; r++)
            acc = fmaf(gf2A[((long)m*FFD + f)*RR + r],
                       gf2B[((long)m*RR + r)*DM + d], acc);
        s_W2c[f][d] = tf32r(acc);
    }
    for (int idx = tid; idx < 4*DM; idx += NTHREADS) {
        int which = idx / DM, i = idx % DM;
        const float* src = (which == 0) ? gln1w : (which == 1) ? gln1b
                         : (which == 2) ? gln2w : gln2b;
        s_ln[which][i] = src[(long)m*DM + i];
    }

    __syncthreads();  // staging visible before any weight reads

    // ---- per-token pipeline (s fast, t slow: minimal warp divergence) ----
    const int s = tid & 7;
    const int t = tid >> 3;
    const long base = ((((long)m*NBATCH + b0 + s)*TT) + t) * DM;

    float4 x0 = *(const float4*)(gx + base);
    float4 x1 = *(const float4*)(gx + base + 4);
    float xr[8] = {x0.x, x0.y, x0.z, x0.w, x1.x, x1.y, x1.z, x1.w};

    // LN1 (exact fp32), output packed to bf16 (feeds only q/k/v: attention branch)
    __nv_bfloat162 hb[4];
    {
        float mean = 0.f;
        #pragma unroll
        for (int i = 0; i < 8; i++) mean += xr[i];
        mean *= 0.125f;
        float var = 0.f;
        #pragma unroll
        for (int i = 0; i < 8; i++) { float d = xr[i] - mean; var += d*d; }
        var *= 0.125f;
        float rstd = rsqrtf(var + 1e-5f);
        float h[8];
        #pragma unroll
        for (int i = 0; i < 8; i++)
            h[i] = (xr[i] - mean) * rstd * s_ln[0][i] + s_ln[1][i];
        #pragma unroll
        for (int i = 0; i < 4; i++) hb[i] = __floats2bfloat162_rn(h[2*i], h[2*i+1]);
    }

    // q pre-scaled by qscale*log2(e) so the attention exp is a bare EX2.
    const float qfold = 0.3535533905932738f * 1.4426950408889634f;

    // QKV in bf16; write K|V row (32B) to shared
    __nv_bfloat162 qb[4];
    {
        #pragma unroll
        for (int i = 0; i < 4; i++)
            qb[i] = __floats2bfloat162_rn(dot8b(hb, s_qkvTb[2*i])   * qfold,
                                          dot8b(hb, s_qkvTb[2*i+1]) * qfold);
        float kvv[16];
        #pragma unroll
        for (int o = 0; o < 8; o++) kvv[o]     = dot8b(hb, s_qkvTb[8 + o]);
        #pragma unroll
        for (int o = 0; o < 8; o++) kvv[8 + o] = dot8b(hb, s_qkvTb[16 + o]);

        float4 pack[2];
        #pragma unroll
        for (int half = 0; half < 2; half++) {
            __nv_bfloat162 p0 = __floats2bfloat162_rn(kvv[8*half+0], kvv[8*half+1]);
            __nv_bfloat162 p1 = __floats2bfloat162_rn(kvv[8*half+2], kvv[8*half+3]);
            __nv_bfloat162 p2 = __floats2bfloat162_rn(kvv[8*half+4], kvv[8*half+5]);
            __nv_bfloat162 p3 = __floats2bfloat162_rn(kvv[8*half+6], kvv[8*half+7]);
            pack[half] = make_float4(*reinterpret_cast<float*>(&p0),
                                     *reinterpret_cast<float*>(&p1),
                                     *reinterpret_cast<float*>(&p2),
                                     *reinterpret_cast<float*>(&p3));
        }
        float4* dst = (float4*)(&s_kv[s][t*8]);
        dst[0] = pack[0];   // K
        dst[1] = pack[1];   // V
    }
    __syncthreads();

    // Single-pass causal attention, fully bf16 (scores tiny => no max needed).
    __nv_bfloat162 av[4] = {__floats2bfloat162_rn(0.f,0.f), __floats2bfloat162_rn(0.f,0.f),
                            __floats2bfloat162_rn(0.f,0.f), __floats2bfloat162_rn(0.f,0.f)};
    float l = 0.f;
    {
        const float* kvp = &s_kv[s][0];
        for (int j = 0; j <= t; j++) {
            const float4* kj = (const float4*)(kvp + j*8);
            float4 kw = kj[0];
            __nv_bfloat162 sc2 = __hmul2(qb[0], *reinterpret_cast<__nv_bfloat162*>(&kw.x));
            sc2 = __hfma2(qb[1], *reinterpret_cast<__nv_bfloat162*>(&kw.y), sc2);
            sc2 = __hfma2(qb[2], *reinterpret_cast<__nv_bfloat162*>(&kw.z), sc2);
            sc2 = __hfma2(qb[3], *reinterpret_cast<__nv_bfloat162*>(&kw.w), sc2);
            float2 sf = __bfloat1622float2(sc2);
            float e = ex2a(sf.x + sf.y);   // q carries qscale*log2e
            l += e;
            __nv_bfloat162 e2 = __float2bfloat162_rn(e);
            float4 vw = kj[1];
            av[0] = __hfma2(e2, *reinterpret_cast<__nv_bfloat162*>(&vw.x), av[0]);
            av[1] = __hfma2(e2, *reinterpret_cast<__nv_bfloat162*>(&vw.y), av[1]);
            av[2] = __hfma2(e2, *reinterpret_cast<__nv_bfloat162*>(&vw.z), av[2]);
            av[3] = __hfma2(e2, *reinterpret_cast<__nv_bfloat162*>(&vw.w), av[3]);
        }
    }
    __nv_bfloat162 yb[4];
    {
        float inv_l = 1.f / l;
        #pragma unroll
        for (int i = 0; i < 4; i++) {
            float2 f = __bfloat1622float2(av[i]);
            yb[i] = __floats2bfloat162_rn(f.x * inv_l, f.y * inv_l);
        }
    }

    // proj (bf16) + residual (fp32)
    float xa[8];
    #pragma unroll
    for (int o = 0; o < 8; o++) xa[o] = xr[o] + dot8b(yb, s_projTb[o]);

    // LN2 (fp32 stats, TF32-quantized output: feeds the precision-critical MLP)
    u64 h2p[4];
    {
        float mean = 0.f;
        #pragma unroll
        for (int i = 0; i < 8; i++) mean += xa[i];
        mean *= 0.125f;
        float var = 0.f;
        #pragma unroll
        for (int i = 0; i < 8; i++) { float d = xa[i] - mean; var += d*d; }
        var *= 0.125f;
        float rstd = rsqrtf(var + 1e-5f);
        float h2[8];
        #pragma unroll
        for (int i = 0; i < 8; i++)
            h2[i] = tf32r((xa[i] - mean) * rstd * s_ln[2][i] + s_ln[3][i]);
        #pragma unroll
        for (int i = 0; i < 4; i++) h2p[i] = pk2(h2[2*i], h2[2*i+1]);
    }

    // MLP (fp32/tf32, paired f-loop with packed GELU):
    // out = xa + gelu(h2@W1c)@W2c
    u64 o01 = 0, o23 = 0, o45 = 0, o67 = 0;
    #pragma unroll
    for (int fp = 0; fp < FFD/2; fp++) {
        const int f0 = 2*fp, f1 = 2*fp + 1;
        float za = dot8p(h2p, s_W1c[f0]);
        float zb = dot8p(h2p, s_W1c[f1]);
        u64 g = gelu2(pk2(za, zb));
        float ga, gbv; upk2(g, ga, gbv);
        ga = tf32r(ga);  gbv = tf32r(gbv);
        u64 z2a = pk2(ga, ga), z2b = pk2(gbv, gbv);
        const ulonglong2* W2a = (const ulonglong2*)s_W2c[f0];
        ulonglong2 a01 = W2a[0], a23 = W2a[1];
        o01 = fma2(z2a, a01.x, o01);
        o23 = fma2(z2a, a01.y, o23);
        o45 = fma2(z2a, a23.x, o45);
        o67 = fma2(z2a, a23.y, o67);
        const ulonglong2* W2b = (const ulonglong2*)s_W2c[f1];
        ulonglong2 b01 = W2b[0], b23 = W2b[1];
        o01 = fma2(z2b, b01.x, o01);
        o23 = fma2(z2b, b01.y, o23);
        o45 = fma2(z2b, b23.x, o45);
        o67 = fma2(z2b, b23.y, o67);
    }

    float o8[8];
    upk2(o01, o8[0], o8[1]); upk2(o23, o8[2], o8[3]);
    upk2(o45, o8[4], o8[5]); upk2(o67, o8[6], o8[7]);

    *(float4*)(gout + base)     = make_float4(xa[0]+o8[0], xa[1]+o8[1], xa[2]+o8[2], xa[3]+o8[3]);
    *(float4*)(gout + base + 4) = make_float4(xa[4]+o8[4], xa[5]+o8[5], xa[6]+o8[6], xa[7]+o8[7]);
}

extern "C" void kernel_launch(void* const* d_in, const int* in_sizes, int n_in,
                              void* d_out, int out_size) {
    const float* x     = (const float*)d_in[0];
    const float* ln1w  = (const float*)d_in[1];
    const float* ln1b  = (const float*)d_in[2];
    const float* qkvw  = (const float*)d_in[3];
    const float* projw = (const float*)d_in[4];
    const float* ln2w  = (const float*)d_in[5];
    const float* ln2b  = (const float*)d_in[6];
    const float* f1A   = (const float*)d_in[7];
    const float* f1B   = (const float*)d_in[8];
    const float* f1W   = (const float*)d_in[9];
    const float* f2A   = (const float*)d_in[10];
    const float* f2B   = (const float*)d_in[11];
    const float* f2W   = (const float*)d_in[12];
    float* out = (float*)d_out;

    block_fused_kernel<<<NBLOCKS, NTHREADS>>>(
        x, ln1w, ln1b, qkvw, projw, ln2w, ln2b,
        f1A, f1B, f1W, f2A, f2B, f2W, out);
}

// round 16
// speedup vs baseline: 6.5900x; 1.0359x over previous
#include <cuda_runtime.h>
#include <cuda_bf16.h>
#include <cstdint>

// Problem constants (fixed by the reference config)
#define DM 8       // d_model
#define TT 33      // seq_len
#define FFD 28     // d_ff
#define RR 3       // ffn_rank
#define NMODELS 8
#define NBATCH 4096

#define NSEQ 8                    // sequences per block
#define NTHREADS (TT * NSEQ)      // 264 threads (best measured shape)
#define BLOCKS_PER_MODEL (NBATCH / NSEQ)   // 512
#define NBLOCKS (NMODELS * BLOCKS_PER_MODEL)

// KV row per token: 8 bf16 K (16B) + 8 bf16 V (16B) = 8 words.
// Per-seq stride 292 words (292 mod 32 = 4 => conflict-free octet access).
#define KVSTRIDE 292

typedef unsigned long long u64;

// ---- TF32 rounding (MLP path matches reference's TF32 einsums) ----
__device__ __forceinline__ float tf32r(float x) {
    uint32_t y;
    asm("cvt.rna.tf32.f32 %0, %1;" : "=r"(y) : "f"(x));
    return __uint_as_float(y);
}

// ---- packed f32x2 ops (sm_100+) ----
__device__ __forceinline__ u64 pk2(float lo, float hi) {
    u64 r; asm("mov.b64 %0, {%1, %2};" : "=l"(r) : "f"(lo), "f"(hi)); return r;
}
__device__ __forceinline__ void upk2(u64 v, float& lo, float& hi) {
    asm("mov.b64 {%0, %1}, %2;" : "=f"(lo), "=f"(hi) : "l"(v));
}
__device__ __forceinline__ u64 fma2(u64 a, u64 b, u64 c) {
    u64 d; asm("fma.rn.f32x2 %0, %1, %2, %3;" : "=l"(d) : "l"(a), "l"(b), "l"(c)); return d;
}
__device__ __forceinline__ u64 mul2(u64 a, u64 b) {
    u64 d; asm("mul.rn.f32x2 %0, %1, %2;" : "=l"(d) : "l"(a), "l"(b)); return d;
}

__device__ __forceinline__ float rcpa(float x) {
    float y; asm("rcp.approx.f32 %0, %1;" : "=f"(y) : "f"(x)); return y;
}
__device__ __forceinline__ float ex2a(float x) {
    float y; asm("ex2.approx.f32 %0, %1;" : "=f"(y) : "f"(x)); return y;
}

__device__ __forceinline__ float dot8p(const u64* a, const float* w) {
    const ulonglong2* W = (const ulonglong2*)w;
    ulonglong2 w01 = W[0], w23 = W[1];
    u64 acc = mul2(a[0], w01.x);
    acc = fma2(a[1], w01.y, acc);
    acc = fma2(a[2], w23.x, acc);
    acc = fma2(a[3], w23.y, acc);
    float lo, hi; upk2(acc, lo, hi);
    return lo + hi;
}

// Output-pair dot: weights in [o-pair][i] bf162 layout (32B row, 2x LDS.128),
// activations duplicated per-dim. 8 HFMA2 -> output pair, already packed.
__device__ __forceinline__ __nv_bfloat162 dotpair(const __nv_bfloat162* abc,
                                                  const __nv_bfloat162* wrow) {
    float4 wv[2];
    wv[0] = ((const float4*)wrow)[0];
    wv[1] = ((const float4*)wrow)[1];
    const __nv_bfloat162* wp = reinterpret_cast<const __nv_bfloat162*>(wv);
    __nv_bfloat162 acc = __hmul2(abc[0], wp[0]);
    #pragma unroll
    for (int i = 1; i < 8; i++) acc = __hfma2(abc[i], wp[i], acc);
    return acc;
}

// Packed-pair exact-erf GELU (A&S 7.1.26, |eps|<=1.5e-7): two z's per call.
__device__ __forceinline__ u64 gelu2(u64 z2) {
    const u64 SIGN2 = 0x8000000080000000ull;
    u64 x2 = mul2(z2, pk2(0.7071067811865475f, 0.7071067811865475f));
    u64 ax = x2 & ~SIGN2;
    u64 den = fma2(pk2(0.3275911f, 0.3275911f), ax, pk2(1.f, 1.f));
    float dlo, dhi; upk2(den, dlo, dhi);
    u64 t = pk2(rcpa(dlo), rcpa(dhi));
    u64 p = fma2(t, pk2(1.061405429f, 1.061405429f), pk2(-1.453152027f, -1.453152027f));
    p = fma2(t, p, pk2(1.421413741f, 1.421413741f));
    p = fma2(t, p, pk2(-0.284496736f, -0.284496736f));
    p = fma2(t, p, pk2(0.254829592f, 0.254829592f));
    p = mul2(p, t);
    u64 xx = mul2(x2, x2);
    u64 w  = mul2(xx, pk2(-1.4426950408889634f, -1.4426950408889634f));
    float wlo, whi; upk2(w, wlo, whi);
    u64 e = pk2(ex2a(wlo), ex2a(whi));
    u64 erfa = fma2(p ^ SIGN2, e, pk2(1.f, 1.f));
    u64 erfv = erfa | (z2 & SIGN2);
    u64 sfac = fma2(erfv, pk2(0.5f, 0.5f), pk2(0.5f, 0.5f));
    return mul2(z2, sfac);
}

__global__ __launch_bounds__(NTHREADS, 4)
void block_fused_kernel(
    const float* __restrict__ gx,
    const float* __restrict__ gln1w, const float* __restrict__ gln1b,
    const float* __restrict__ gqkv,  const float* __restrict__ gproj,
    const float* __restrict__ gln2w, const float* __restrict__ gln2b,
    const float* __restrict__ gf1A,  const float* __restrict__ gf1B,
    const float* __restrict__ gf1W,  const float* __restrict__ gf2A,
    const float* __restrict__ gf2B,  const float* __restrict__ gf2W,
    float* __restrict__ gout)
{
    // Attention weights in output-pair bf162 layout: row p holds
    // (W[i][2p], W[i][2p+1]) for i = 0..7 (32B row). p: 0-3 q, 4-7 k, 8-11 v.
    __shared__ __align__(16) __nv_bfloat162 s_qkvP[12][8];
    __shared__ __align__(16) __nv_bfloat162 s_projP[4][8];
    __shared__ __align__(16) float s_W1c[FFD][DM];     // [f][i] = f1Wf + f1A@f1B
    __shared__ __align__(16) float s_W2c[FFD][DM];     // [f][d] = f2Wf + f2A@f2B
    __shared__ __align__(16) float s_ln[4][DM];        // ln1w, ln1b, ln2w, ln2b
    __shared__ __align__(16) float s_kv[NSEQ][KVSTRIDE]; // bf16 K(16B)|V(16B) per token

    const int tid = threadIdx.x;
    const int m  = blockIdx.x / BLOCKS_PER_MODEL;
    const int b0 = (blockIdx.x % BLOCKS_PER_MODEL) * NSEQ;

    // ---- stage weights ----
    for (int idx = tid; idx < 12*8; idx += NTHREADS) {
        int p = idx / 8, i = idx % 8;
        const float* wrow = gqkv + ((long)m*DM + i)*(3*DM) + 2*p;
        s_qkvP[p][i] = __floats2bfloat162_rn(wrow[0], wrow[1]);
    }
    for (int idx = tid; idx < 4*8; idx += NTHREADS) {
        int p = idx / 8, i = idx % 8;
        const float* wrow = gproj + ((long)m*DM + i)*DM + 2*p;
        s_projP[p][i] = __floats2bfloat162_rn(wrow[0], wrow[1]);
    }
    for (int idx = tid; idx < FFD*DM; idx += NTHREADS) {
        int f = idx / DM, i = idx % DM;
        float acc = gf1W[((long)m*DM + i)*FFD + f];
        #pragma unroll
        for (int r = 0; r < RR; r++)
            acc = fmaf(gf1A[((long)m*DM + i)*RR + r],
                       gf1B[((long)m*RR + r)*FFD + f], acc);
        s_W1c[f][i] = tf32r(acc);
    }
    for (int idx = tid; idx < FFD*DM; idx += NTHREADS) {
        int f = idx / DM, d = idx % DM;
        float acc = gf2W[((long)m*FFD + f)*DM + d];
        #pragma unroll
        for (int r = 0; r < RR; r++)
            acc = fmaf(gf2A[((long)m*FFD + f)*RR + r],
                       gf2B[((long)m*RR + r)*DM + d], acc);
        s_W2c[f][d] = tf32r(acc);
    }
    for (int idx = tid; idx < 4*DM; idx += NTHREADS) {
        int which = idx / DM, i = idx % DM;
        const float* src = (which == 0) ? gln1w : (which == 1) ? gln1b
                         : (which == 2) ? gln2w : gln2b;
        s_ln[which][i] = src[(long)m*DM + i];
    }

    __syncthreads();  // staging visible before any weight reads

    // ---- per-token pipeline (s fast, t slow: minimal warp divergence) ----
    const int s = tid & 7;
    const int t = tid >> 3;
    const long base = ((((long)m*NBATCH + b0 + s)*TT) + t) * DM;

    float4 x0 = *(const float4*)(gx + base);
    float4 x1 = *(const float4*)(gx + base + 4);
    float xr[8] = {x0.x, x0.y, x0.z, x0.w, x1.x, x1.y, x1.z, x1.w};

    // LN1 (exact fp32), output duplicated per-dim in bf162 for pair-dots
    __nv_bfloat162 hbc[8];
    {
        float mean = 0.f;
        #pragma unroll
        for (int i = 0; i < 8; i++) mean += xr[i];
        mean *= 0.125f;
        float var = 0.f;
        #pragma unroll
        for (int i = 0; i < 8; i++) { float d = xr[i] - mean; var += d*d; }
        var *= 0.125f;
        float rstd = rsqrtf(var + 1e-5f);
        #pragma unroll
        for (int i = 0; i < 8; i++)
            hbc[i] = __float2bfloat162_rn((xr[i] - mean) * rstd * s_ln[0][i] + s_ln[1][i]);
    }

    // q pre-scaled by qscale*log2(e) so the attention exp is a bare EX2.
    const __nv_bfloat162 qfold2 =
        __float2bfloat162_rn(0.3535533905932738f * 1.4426950408889634f);

    // QKV via pair-dots: outputs arrive pre-packed in dim-pair bf162 form.
    __nv_bfloat162 qb[4];
    {
        #pragma unroll
        for (int p = 0; p < 4; p++)
            qb[p] = __hmul2(dotpair(hbc, s_qkvP[p]), qfold2);

        __nv_bfloat162 kv[8];
        #pragma unroll
        for (int p = 0; p < 8; p++)
            kv[p] = dotpair(hbc, s_qkvP[4 + p]);   // 0-3: K pairs, 4-7: V pairs

        float4* dst = (float4*)(&s_kv[s][t*8]);
        dst[0] = *reinterpret_cast<float4*>(&kv[0]);   // K
        dst[1] = *reinterpret_cast<float4*>(&kv[4]);   // V
    }
    __syncthreads();

    // Single-pass causal attention, fully bf16 (scores tiny => no max needed).
    __nv_bfloat162 av[4] = {__floats2bfloat162_rn(0.f,0.f), __floats2bfloat162_rn(0.f,0.f),
                            __floats2bfloat162_rn(0.f,0.f), __floats2bfloat162_rn(0.f,0.f)};
    float l = 0.f;
    {
        const float* kvp = &s_kv[s][0];
        for (int j = 0; j <= t; j++) {
            const float4* kj = (const float4*)(kvp + j*8);
            float4 kw = kj[0];
            __nv_bfloat162 sc2 = __hmul2(qb[0], *reinterpret_cast<__nv_bfloat162*>(&kw.x));
            sc2 = __hfma2(qb[1], *reinterpret_cast<__nv_bfloat162*>(&kw.y), sc2);
            sc2 = __hfma2(qb[2], *reinterpret_cast<__nv_bfloat162*>(&kw.z), sc2);
            sc2 = __hfma2(qb[3], *reinterpret_cast<__nv_bfloat162*>(&kw.w), sc2);
            float2 sf = __bfloat1622float2(sc2);
            float e = ex2a(sf.x + sf.y);   // q carries qscale*log2e
            l += e;
            __nv_bfloat162 e2 = __float2bfloat162_rn(e);
            float4 vw = kj[1];
            av[0] = __hfma2(e2, *reinterpret_cast<__nv_bfloat162*>(&vw.x), av[0]);
            av[1] = __hfma2(e2, *reinterpret_cast<__nv_bfloat162*>(&vw.y), av[1]);
            av[2] = __hfma2(e2, *reinterpret_cast<__nv_bfloat162*>(&vw.z), av[2]);
            av[3] = __hfma2(e2, *reinterpret_cast<__nv_bfloat162*>(&vw.w), av[3]);
        }
    }
    // Normalize and duplicate y per-dim for the proj pair-dot.
    __nv_bfloat162 ybc[8];
    {
        float inv_l = 1.f / l;
        #pragma unroll
        for (int i = 0; i < 4; i++) {
            float2 f = __bfloat1622float2(av[i]);
            ybc[2*i]   = __float2bfloat162_rn(f.x * inv_l);
            ybc[2*i+1] = __float2bfloat162_rn(f.y * inv_l);
        }
    }

    // proj (pair-dots) + residual (fp32)
    float xa[8];
    #pragma unroll
    for (int p = 0; p < 4; p++) {
        float2 pr = __bfloat1622float2(dotpair(ybc, s_projP[p]));
        xa[2*p]   = xr[2*p]   + pr.x;
        xa[2*p+1] = xr[2*p+1] + pr.y;
    }

    // LN2 (fp32 stats, TF32-quantized output: feeds the precision-critical MLP)
    u64 h2p[4];
    {
        float mean = 0.f;
        #pragma unroll
        for (int i = 0; i < 8; i++) mean += xa[i];
        mean *= 0.125f;
        float var = 0.f;
        #pragma unroll
        for (int i = 0; i < 8; i++) { float d = xa[i] - mean; var += d*d; }
        var *= 0.125f;
        float rstd = rsqrtf(var + 1e-5f);
        float h2[8];
        #pragma unroll
        for (int i = 0; i < 8; i++)
            h2[i] = tf32r((xa[i] - mean) * rstd * s_ln[2][i] + s_ln[3][i]);
        #pragma unroll
        for (int i = 0; i < 4; i++) h2p[i] = pk2(h2[2*i], h2[2*i+1]);
    }

    // MLP (fp32/tf32, paired f-loop with packed GELU): out = xa + gelu(h2@W1c)@W2c
    u64 o01 = 0, o23 = 0, o45 = 0, o67 = 0;
    #pragma unroll
    for (int fp = 0; fp < FFD/2; fp++) {
        const int f0 = 2*fp, f1 = 2*fp + 1;
        float za = dot8p(h2p, s_W1c[f0]);
        float zb = dot8p(h2p, s_W1c[f1]);
        u64 g = gelu2(pk2(za, zb));
        float ga, gbv; upk2(g, ga, gbv);
        ga = tf32r(ga);  gbv = tf32r(gbv);
        u64 z2a = pk2(ga, ga), z2b = pk2(gbv, gbv);
        const ulonglong2* W2a = (const ulonglong2*)s_W2c[f0];
        ulonglong2 a01 = W2a[0], a23 = W2a[1];
        o01 = fma2(z2a, a01.x, o01);
        o23 = fma2(z2a, a01.y, o23);
        o45 = fma2(z2a, a23.x, o45);
        o67 = fma2(z2a, a23.y, o67);
        const ulonglong2* W2b = (const ulonglong2*)s_W2c[f1];
        ulonglong2 b01 = W2b[0], b23 = W2b[1];
        o01 = fma2(z2b, b01.x, o01);
        o23 = fma2(z2b, b01.y, o23);
        o45 = fma2(z2b, b23.x, o45);
        o67 = fma2(z2b, b23.y, o67);
    }

    float o8[8];
    upk2(o01, o8[0], o8[1]); upk2(o23, o8[2], o8[3]);
    upk2(o45, o8[4], o8[5]); upk2(o67, o8[6], o8[7]);

    *(float4*)(gout + base)     = make_float4(xa[0]+o8[0], xa[1]+o8[1], xa[2]+o8[2], xa[3]+o8[3]);
    *(float4*)(gout + base + 4) = make_float4(xa[4]+o8[4], xa[5]+o8[5], xa[6]+o8[6], xa[7]+o8[7]);
}

extern "C" void kernel_launch(void* const* d_in, const int* in_sizes, int n_in,
                              void* d_out, int out_size) {
    const float* x     = (const float*)d_in[0];
    const float* ln1w  = (const float*)d_in[1];
    const float* ln1b  = (const float*)d_in[2];
    const float* qkvw  = (const float*)d_in[3];
    const float* projw = (const float*)d_in[4];
    const float* ln2w  = (const float*)d_in[5];
    const float* ln2b  = (const float*)d_in[6];
    const float* f1A   = (const float*)d_in[7];
    const float* f1B   = (const float*)d_in[8];
    const float* f1W   = (const float*)d_in[9];
    const float* f2A   = (const float*)d_in[10];
    const float* f2B   = (const float*)d_in[11];
    const float* f2W   = (const float*)d_in[12];
    float* out = (float*)d_out;

    block_fused_kernel<<<NBLOCKS, NTHREADS>>>(
        x, ln1w, ln1b, qkvw, projw, ln2w, ln2b,
        f1A, f1B, f1W, f2A, f2B, f2W, out);
}

// round 17
// speedup vs baseline: 7.0779x; 1.0740x over previous
#include <cuda_runtime.h>
#include <cuda_bf16.h>
#include <cstdint>

// Problem constants (fixed by the reference config)
#define DM 8       // d_model
#define TT 33      // seq_len
#define FFD 28     // d_ff
#define RR 3       // ffn_rank
#define NMODELS 8
#define NBATCH 4096

#define NSEQ 8                    // sequences per block
#define NTHREADS (TT * NSEQ)      // 264 threads (best measured shape)
#define BLOCKS_PER_MODEL (NBATCH / NSEQ)   // 512
#define NBLOCKS (NMODELS * BLOCKS_PER_MODEL)

// KV row per token: 8 bf16 K (16B) + 8 bf16 V (16B) = 8 words.
// Per-seq stride 292 words (292 mod 32 = 4 => conflict-free octet access).
#define KVSTRIDE 292

typedef unsigned long long u64;

// ---- TF32 rounding (MLP path matches reference's TF32 einsums) ----
__device__ __forceinline__ float tf32r(float x) {
    uint32_t y;
    asm("cvt.rna.tf32.f32 %0, %1;" : "=r"(y) : "f"(x));
    return __uint_as_float(y);
}

// ---- packed f32x2 ops (sm_100+) ----
__device__ __forceinline__ u64 pk2(float lo, float hi) {
    u64 r; asm("mov.b64 %0, {%1, %2};" : "=l"(r) : "f"(lo), "f"(hi)); return r;
}
__device__ __forceinline__ void upk2(u64 v, float& lo, float& hi) {
    asm("mov.b64 {%0, %1}, %2;" : "=f"(lo), "=f"(hi) : "l"(v));
}
__device__ __forceinline__ u64 fma2(u64 a, u64 b, u64 c) {
    u64 d; asm("fma.rn.f32x2 %0, %1, %2, %3;" : "=l"(d) : "l"(a), "l"(b), "l"(c)); return d;
}
__device__ __forceinline__ u64 mul2(u64 a, u64 b) {
    u64 d; asm("mul.rn.f32x2 %0, %1, %2;" : "=l"(d) : "l"(a), "l"(b)); return d;
}

__device__ __forceinline__ float rcpa(float x) {
    float y; asm("rcp.approx.f32 %0, %1;" : "=f"(y) : "f"(x)); return y;
}
__device__ __forceinline__ float ex2a(float x) {
    float y; asm("ex2.approx.f32 %0, %1;" : "=f"(y) : "f"(x)); return y;
}

// Output-pair dot (attention): weights in [o-pair][i] bf162 layout, activations
// duplicated per-dim. 8 HFMA2 -> output pair, already packed.
__device__ __forceinline__ __nv_bfloat162 dotpair(const __nv_bfloat162* abc,
                                                  const __nv_bfloat162* wrow) {
    float4 wv[2];
    wv[0] = ((const float4*)wrow)[0];
    wv[1] = ((const float4*)wrow)[1];
    const __nv_bfloat162* wp = reinterpret_cast<const __nv_bfloat162*>(wv);
    __nv_bfloat162 acc = __hmul2(abc[0], wp[0]);
    #pragma unroll
    for (int i = 1; i < 8; i++) acc = __hfma2(abc[i], wp[i], acc);
    return acc;
}

// Packed-pair tanh-form GELU, algebraically minimized:
//   gelu(z) = z * (1 - r),  r = 1 / (2^(K*z*(1 + c*z^2)) + 1)
// with K = 2*log2(e)*0.7978845608 (exp base folded into EX2).
// Deviation from exact erf-gelu < 5e-5 abs for |z| <~ 1.1 (our z std ~0.54);
// enters the output attenuated by W2c -> ~5e-5 rel contribution. ~14 ops/pair.
__device__ __forceinline__ u64 gelu2t(u64 z2) {
    const u64 SIGN2 = 0x8000000080000000ull;
    const float K  = 2.3021862764843453f;     // 2*log2e*sqrt(2/pi)
    const float KC = 0.1029422631912507f;     // K*0.044715
    u64 zz = mul2(z2, z2);
    u64 w  = fma2(zz, pk2(KC, KC), pk2(K, K));
    u64 tt = mul2(z2, w);                     // K*z*(1+c*z^2)
    float tlo, thi; upk2(tt, tlo, thi);
    u64 e = pk2(ex2a(tlo), ex2a(thi));        // 2^t = e^{2u}
    u64 den = fma2(e, pk2(1.f, 1.f), pk2(1.f, 1.f));   // e+1
    float dlo, dhi; upk2(den, dlo, dhi);
    u64 r = pk2(rcpa(dlo), rcpa(dhi));
    return fma2(z2, r ^ SIGN2, z2);           // z*(1-r)
}

__global__ __launch_bounds__(NTHREADS, 4)
void block_fused_kernel(
    const float* __restrict__ gx,
    const float* __restrict__ gln1w, const float* __restrict__ gln1b,
    const float* __restrict__ gqkv,  const float* __restrict__ gproj,
    const float* __restrict__ gln2w, const float* __restrict__ gln2b,
    const float* __restrict__ gf1A,  const float* __restrict__ gf1B,
    const float* __restrict__ gf1W,  const float* __restrict__ gf2A,
    const float* __restrict__ gf2B,  const float* __restrict__ gf2W,
    float* __restrict__ gout)
{
    // Attention weights in output-pair bf162 layout (p: 0-3 q, 4-7 k, 8-11 v).
    __shared__ __align__(16) __nv_bfloat162 s_qkvP[12][8];
    __shared__ __align__(16) __nv_bfloat162 s_projP[4][8];
    // fc1 combined weights in output-pair f32x2 layout: row fp holds
    // (W1c[2fp][i], W1c[2fp+1][i]) for i = 0..7 (64B row).
    __shared__ __align__(16) u64 s_W1P[FFD/2][DM];
    __shared__ __align__(16) float s_W2c[FFD][DM];     // [f][d] = f2Wf + f2A@f2B
    __shared__ __align__(16) float s_ln[4][DM];        // ln1w, ln1b, ln2w, ln2b
    __shared__ __align__(16) float s_kv[NSEQ][KVSTRIDE]; // bf16 K(16B)|V(16B) per token

    const int tid = threadIdx.x;
    const int m  = blockIdx.x / BLOCKS_PER_MODEL;
    const int b0 = (blockIdx.x % BLOCKS_PER_MODEL) * NSEQ;

    // ---- stage weights ----
    for (int idx = tid; idx < 12*8; idx += NTHREADS) {
        int p = idx / 8, i = idx % 8;
        const float* wrow = gqkv + ((long)m*DM + i)*(3*DM) + 2*p;
        s_qkvP[p][i] = __floats2bfloat162_rn(wrow[0], wrow[1]);
    }
    for (int idx = tid; idx < 4*8; idx += NTHREADS) {
        int p = idx / 8, i = idx % 8;
        const float* wrow = gproj + ((long)m*DM + i)*DM + 2*p;
        s_projP[p][i] = __floats2bfloat162_rn(wrow[0], wrow[1]);
    }
    // W1P: combined fc1 (Wf + A@B), tf32-rounded, packed by output pair
    for (int idx = tid; idx < (FFD/2)*DM; idx += NTHREADS) {
        int fp = idx / DM, i = idx % DM;
        float v[2];
        #pragma unroll
        for (int h = 0; h < 2; h++) {
            int f = 2*fp + h;
            float acc = gf1W[((long)m*DM + i)*FFD + f];
            #pragma unroll
            for (int r = 0; r < RR; r++)
                acc = fmaf(gf1A[((long)m*DM + i)*RR + r],
                           gf1B[((long)m*RR + r)*FFD + f], acc);
            v[h] = tf32r(acc);
        }
        s_W1P[fp][i] = pk2(v[0], v[1]);
    }
    for (int idx = tid; idx < FFD*DM; idx += NTHREADS) {
        int f = idx / DM, d = idx % DM;
        float acc = gf2W[((long)m*FFD + f)*DM + d];
        #pragma unroll
        for (int r = 0; r < RR; r++)
            acc = fmaf(gf2A[((long)m*FFD + f)*RR + r],
                       gf2B[((long)m*RR + r)*DM + d], acc);
        s_W2c[f][d] = tf32r(acc);
    }
    for (int idx = tid; idx < 4*DM; idx += NTHREADS) {
        int which = idx / DM, i = idx % DM;
        const float* src = (which == 0) ? gln1w : (which == 1) ? gln1b
                         : (which == 2) ? gln2w : gln2b;
        s_ln[which][i] = src[(long)m*DM + i];
    }

    __syncthreads();  // staging visible before any weight reads

    // ---- per-token pipeline (s fast, t slow: minimal warp divergence) ----
    const int s = tid & 7;
    const int t = tid >> 3;
    const long base = ((((long)m*NBATCH + b0 + s)*TT) + t) * DM;

    float4 x0 = *(const float4*)(gx + base);
    float4 x1 = *(const float4*)(gx + base + 4);
    float xr[8] = {x0.x, x0.y, x0.z, x0.w, x1.x, x1.y, x1.z, x1.w};

    // LN1 (exact fp32), output duplicated per-dim in bf162 for pair-dots
    __nv_bfloat162 hbc[8];
    {
        float mean = 0.f;
        #pragma unroll
        for (int i = 0; i < 8; i++) mean += xr[i];
        mean *= 0.125f;
        float var = 0.f;
        #pragma unroll
        for (int i = 0; i < 8; i++) { float d = xr[i] - mean; var += d*d; }
        var *= 0.125f;
        float rstd = rsqrtf(var + 1e-5f);
        #pragma unroll
        for (int i = 0; i < 8; i++)
            hbc[i] = __float2bfloat162_rn((xr[i] - mean) * rstd * s_ln[0][i] + s_ln[1][i]);
    }

    // q pre-scaled by qscale*log2(e) so the attention exp is a bare EX2.
    const __nv_bfloat162 qfold2 =
        __float2bfloat162_rn(0.3535533905932738f * 1.4426950408889634f);

    // QKV via pair-dots: outputs arrive pre-packed in dim-pair bf162 form.
    __nv_bfloat162 qb[4];
    {
        #pragma unroll
        for (int p = 0; p < 4; p++)
            qb[p] = __hmul2(dotpair(hbc, s_qkvP[p]), qfold2);

        __nv_bfloat162 kv[8];
        #pragma unroll
        for (int p = 0; p < 8; p++)
            kv[p] = dotpair(hbc, s_qkvP[4 + p]);   // 0-3: K pairs, 4-7: V pairs

        float4* dst = (float4*)(&s_kv[s][t*8]);
        dst[0] = *reinterpret_cast<float4*>(&kv[0]);   // K
        dst[1] = *reinterpret_cast<float4*>(&kv[4]);   // V
    }
    __syncthreads();

    // Single-pass causal attention, fully bf16 (scores tiny => no max needed).
    __nv_bfloat162 av[4] = {__floats2bfloat162_rn(0.f,0.f), __floats2bfloat162_rn(0.f,0.f),
                            __floats2bfloat162_rn(0.f,0.f), __floats2bfloat162_rn(0.f,0.f)};
    float l = 0.f;
    {
        const float* kvp = &s_kv[s][0];
        for (int j = 0; j <= t; j++) {
            const float4* kj = (const float4*)(kvp + j*8);
            float4 kw = kj[0];
            __nv_bfloat162 sc2 = __hmul2(qb[0], *reinterpret_cast<__nv_bfloat162*>(&kw.x));
            sc2 = __hfma2(qb[1], *reinterpret_cast<__nv_bfloat162*>(&kw.y), sc2);
            sc2 = __hfma2(qb[2], *reinterpret_cast<__nv_bfloat162*>(&kw.z), sc2);
            sc2 = __hfma2(qb[3], *reinterpret_cast<__nv_bfloat162*>(&kw.w), sc2);
            float2 sf = __bfloat1622float2(sc2);
            float e = ex2a(sf.x + sf.y);   // q carries qscale*log2e
            l += e;
            __nv_bfloat162 e2 = __float2bfloat162_rn(e);
            float4 vw = kj[1];
            av[0] = __hfma2(e2, *reinterpret_cast<__nv_bfloat162*>(&vw.x), av[0]);
            av[1] = __hfma2(e2, *reinterpret_cast<__nv_bfloat162*>(&vw.y), av[1]);
            av[2] = __hfma2(e2, *reinterpret_cast<__nv_bfloat162*>(&vw.z), av[2]);
            av[3] = __hfma2(e2, *reinterpret_cast<__nv_bfloat162*>(&vw.w), av[3]);
        }
    }
    // Normalize and duplicate y per-dim for the proj pair-dot.
    __nv_bfloat162 ybc[8];
    {
        float inv_l = 1.f / l;
        #pragma unroll
        for (int i = 0; i < 4; i++) {
            float2 f = __bfloat1622float2(av[i]);
            ybc[2*i]   = __float2bfloat162_rn(f.x * inv_l);
            ybc[2*i+1] = __float2bfloat162_rn(f.y * inv_l);
        }
    }

    // proj (pair-dots) + residual (fp32)
    float xa[8];
    #pragma unroll
    for (int p = 0; p < 4; p++) {
        float2 pr = __bfloat1622float2(dotpair(ybc, s_projP[p]));
        xa[2*p]   = xr[2*p]   + pr.x;
        xa[2*p+1] = xr[2*p+1] + pr.y;
    }

    // LN2 (fp32 stats, TF32-quantized output, duplicated per-dim as f32x2)
    u64 h2d[8];
    {
        float mean = 0.f;
        #pragma unroll
        for (int i = 0; i < 8; i++) mean += xa[i];
        mean *= 0.125f;
        float var = 0.f;
        #pragma unroll
        for (int i = 0; i < 8; i++) { float d = xa[i] - mean; var += d*d; }
        var *= 0.125f;
        float rstd = rsqrtf(var + 1e-5f);
        #pragma unroll
        for (int i = 0; i < 8; i++) {
            float h = tf32r((xa[i] - mean) * rstd * s_ln[2][i] + s_ln[3][i]);
            h2d[i] = pk2(h, h);
        }
    }

    // MLP (fp32/tf32): pair-layout fc1 (8 fma2 -> z-pair), tanh-gelu, fc2.
    u64 o01 = 0, o23 = 0, o45 = 0, o67 = 0;
    #pragma unroll
    for (int fp = 0; fp < FFD/2; fp++) {
        const ulonglong2* W1 = (const ulonglong2*)s_W1P[fp];
        ulonglong2 wA = W1[0], wB = W1[1], wC = W1[2], wD = W1[3];
        u64 z2 = mul2(h2d[0], wA.x);
        z2 = fma2(h2d[1], wA.y, z2);
        z2 = fma2(h2d[2], wB.x, z2);
        z2 = fma2(h2d[3], wB.y, z2);
        z2 = fma2(h2d[4], wC.x, z2);
        z2 = fma2(h2d[5], wC.y, z2);
        z2 = fma2(h2d[6], wD.x, z2);
        z2 = fma2(h2d[7], wD.y, z2);

        u64 g = gelu2t(z2);
        float ga, gbv; upk2(g, ga, gbv);
        ga = tf32r(ga);  gbv = tf32r(gbv);
        u64 z2a = pk2(ga, ga), z2b = pk2(gbv, gbv);

        const int f0 = 2*fp, f1 = 2*fp + 1;
        const ulonglong2* W2a = (const ulonglong2*)s_W2c[f0];
        ulonglong2 a01 = W2a[0], a23 = W2a[1];
        o01 = fma2(z2a, a01.x, o01);
        o23 = fma2(z2a, a01.y, o23);
        o45 = fma2(z2a, a23.x, o45);
        o67 = fma2(z2a, a23.y, o67);
        const ulonglong2* W2b = (const ulonglong2*)s_W2c[f1];
        ulonglong2 b01 = W2b[0], b23 = W2b[1];
        o01 = fma2(z2b, b01.x, o01);
        o23 = fma2(z2b, b01.y, o23);
        o45 = fma2(z2b, b23.x, o45);
        o67 = fma2(z2b, b23.y, o67);
    }

    float o8[8];
    upk2(o01, o8[0], o8[1]); upk2(o23, o8[2], o8[3]);
    upk2(o45, o8[4], o8[5]); upk2(o67, o8[6], o8[7]);

    *(float4*)(gout + base)     = make_float4(xa[0]+o8[0], xa[1]+o8[1], xa[2]+o8[2], xa[3]+o8[3]);
    *(float4*)(gout + base + 4) = make_float4(xa[4]+o8[4], xa[5]+o8[5], xa[6]+o8[6], xa[7]+o8[7]);
}

extern "C" void kernel_launch(void* const* d_in, const int* in_sizes, int n_in,
                              void* d_out, int out_size) {
    const float* x     = (const float*)d_in[0];
    const float* ln1w  = (const float*)d_in[1];
    const float* ln1b  = (const float*)d_in[2];
    const float* qkvw  = (const float*)d_in[3];
    const float* projw = (const float*)d_in[4];
    const float* ln2w  = (const float*)d_in[5];
    const float* ln2b  = (const float*)d_in[6];
    const float* f1A   = (const float*)d_in[7];
    const float* f1B   = (const float*)d_in[8];
    const float* f1W   = (const float*)d_in[9];
    const float* f2A   = (const float*)d_in[10];
    const float* f2B   = (const float*)d_in[11];
    const float* f2W   = (const float*)d_in[12];
    float* out = (float*)d_out;

    block_fused_kernel<<<NBLOCKS, NTHREADS>>>(
        x, ln1w, ln1b, qkvw, projw, ln2w, ln2b,
        f1A, f1B, f1W, f2A, f2B, f2W, out);
}